// round 1
// baseline (speedup 1.0000x reference)
#include <cuda_runtime.h>
#include <math.h>

#define BB 2
#define SS 2048
#define HID 4096
#define NH 32
#define NKV 8
#define HD 128
#define BSR (BB*SS)          // 4096 total rows
#define NREP (NH/NKV)        // 4

// ---------------- scratch (__device__ globals; no allocation allowed) ----------
__device__ float g_lin[(size_t)BSR * HID];            // 64MB: q/k/v linear scratch
__device__ float g_q [(size_t)BB * NH  * SS * HD];    // 64MB: [b,h,s,d]
__device__ float g_k [(size_t)BB * NKV * SS * HD];    // 16MB
__device__ float g_v [(size_t)BB * NKV * SS * HD];    // 16MB
__device__ float g_attn[(size_t)BSR * HID];           // 64MB: [b*s, h*d]

// ---------------- fp32 NT GEMM: C[m,n] = sum_k A[m,k] * B[n,k] ------------------
// BM=BN=128, BK=16, 256 threads, 8x8 micro-tile per thread.
__global__ __launch_bounds__(256) void sgemm_nt(
    const float* __restrict__ A, const float* __restrict__ Bm,
    float* __restrict__ C, int M, int N, int K)
{
    __shared__ float As[16][132];
    __shared__ float Bs[16][132];

    const int tid = threadIdx.x;
    const int m0 = blockIdx.y * 128;
    const int n0 = blockIdx.x * 128;
    const int tr = tid >> 4;          // 0..15
    const int tc = tid & 15;          // 0..15
    const int lrow = tid >> 2;        // 0..63
    const int lcol = (tid & 3) * 4;   // 0,4,8,12

    float acc[8][8];
#pragma unroll
    for (int i = 0; i < 8; i++)
#pragma unroll
        for (int j = 0; j < 8; j++) acc[i][j] = 0.f;

    for (int k0 = 0; k0 < K; k0 += 16) {
#pragma unroll
        for (int half = 0; half < 2; half++) {
            const int r = lrow + half * 64;
            float4 av = *(const float4*)&A[(size_t)(m0 + r) * K + k0 + lcol];
            As[lcol + 0][r] = av.x; As[lcol + 1][r] = av.y;
            As[lcol + 2][r] = av.z; As[lcol + 3][r] = av.w;
            float4 bv = *(const float4*)&Bm[(size_t)(n0 + r) * K + k0 + lcol];
            Bs[lcol + 0][r] = bv.x; Bs[lcol + 1][r] = bv.y;
            Bs[lcol + 2][r] = bv.z; Bs[lcol + 3][r] = bv.w;
        }
        __syncthreads();
#pragma unroll
        for (int k = 0; k < 16; k++) {
            float a[8], b[8];
            *(float4*)&a[0] = *(const float4*)&As[k][tr * 8];
            *(float4*)&a[4] = *(const float4*)&As[k][tr * 8 + 4];
            *(float4*)&b[0] = *(const float4*)&Bs[k][tc * 8];
            *(float4*)&b[4] = *(const float4*)&Bs[k][tc * 8 + 4];
#pragma unroll
            for (int i = 0; i < 8; i++)
#pragma unroll
                for (int j = 0; j < 8; j++)
                    acc[i][j] = fmaf(a[i], b[j], acc[i][j]);
        }
        __syncthreads();
    }
#pragma unroll
    for (int i = 0; i < 8; i++) {
        float* crow = &C[(size_t)(m0 + tr * 8 + i) * N + n0 + tc * 8];
        *(float4*)&crow[0] = make_float4(acc[i][0], acc[i][1], acc[i][2], acc[i][3]);
        *(float4*)&crow[4] = make_float4(acc[i][4], acc[i][5], acc[i][6], acc[i][7]);
    }
}

// ---------------- RoPE + [b,s,h,d] -> [b,h,s,d] transpose ----------------------
// blockIdx.x = ((b*nh)+h)*S + s ; threadIdx.x = d
__global__ __launch_bounds__(HD) void rope_kernel(
    const float* __restrict__ lin, const float* __restrict__ cp,
    const float* __restrict__ sp, float* __restrict__ out,
    int nh, float scale)
{
    const int idx = blockIdx.x;
    const int s  = idx % SS;
    const int bh = idx / SS;
    const int h  = bh % nh;
    const int b  = bh / nh;
    const int d  = threadIdx.x;

    const size_t in_row = ((size_t)(b * SS + s)) * (size_t)(nh * HD) + (size_t)h * HD;
    const float x  = lin[in_row + d];
    const float xr = (d < HD / 2) ? -lin[in_row + d + HD / 2] : lin[in_row + d - HD / 2];
    const size_t cs = ((size_t)b * SS + s) * HD + d;
    out[(size_t)idx * HD + d] = (x * cp[cs] + xr * sp[cs]) * scale;
}

// ---------------- V transpose [b,s,kv,d] -> [b,kv,s,d] -------------------------
__global__ __launch_bounds__(HD) void vtrans_kernel(
    const float* __restrict__ lin, float* __restrict__ out)
{
    const int idx = blockIdx.x;                // ((b*NKV)+h)*S + s
    const int s  = idx % SS;
    const int bh = idx / SS;
    const int h  = bh % NKV;
    const int b  = bh / NKV;
    const int d  = threadIdx.x;
    out[(size_t)idx * HD + d] =
        lin[((size_t)(b * SS + s)) * (size_t)(NKV * HD) + (size_t)h * HD + d];
}

// ---------------- causal flash attention (fp32, online softmax) ----------------
// BQ=BK=64, 256 threads (16x16), 4x4 S-tile and 4x8 O-tile per thread.
#define BQ 64
#define BKT 64
#define QSTR 132     // padded row stride for q/k/v tiles (float4-aligned)
#define PSTR 65
#define ATTN_SMEM_FLOATS (BQ*QSTR + BKT*QSTR + BKT*QSTR + BQ*PSTR)
#define ATTN_SMEM_BYTES  (ATTN_SMEM_FLOATS * 4)

__global__ __launch_bounds__(256) void attn_kernel(
    const float* __restrict__ q, const float* __restrict__ k,
    const float* __restrict__ v, float* __restrict__ out)
{
    extern __shared__ float smem[];
    float* q_s = smem;                       // [BQ][QSTR]
    float* k_s = q_s + BQ * QSTR;            // [BKT][QSTR]
    float* v_s = k_s + BKT * QSTR;           // [BKT][QSTR]
    float* p_s = v_s + BKT * QSTR;           // [BQ][PSTR]

    const int tid = threadIdx.x;
    const int ty = tid >> 4;                 // 0..15
    const int tx = tid & 15;                 // 0..15
    const int qt = blockIdx.x;
    const int h  = blockIdx.y;
    const int b  = blockIdx.z;
    const int q0 = qt * BQ;
    const int hk = h / NREP;

    const float* qg = q + ((size_t)((b * NH + h) * SS) + q0) * HD;
    const float* kg = k + ((size_t)(b * NKV + hk) * SS) * HD;
    const float* vg = v + ((size_t)(b * NKV + hk) * SS) * HD;

    // load Q tile (contiguous 64x128)
    for (int i = tid; i < BQ * HD / 4; i += 256) {
        const int r = i >> 5, c4 = i & 31;
        float4 val = ((const float4*)qg)[i];
        float* dst = &q_s[r * QSTR + c4 * 4];
        dst[0] = val.x; dst[1] = val.y; dst[2] = val.z; dst[3] = val.w;
    }
    __syncthreads();

    float m_r[4], l_r[4], o[4][8];
#pragma unroll
    for (int i = 0; i < 4; i++) {
        m_r[i] = -1e30f; l_r[i] = 0.f;
#pragma unroll
        for (int c = 0; c < 8; c++) o[i][c] = 0.f;
    }

    const int nkt = qt + 1;                  // causal: only tiles up to diagonal
    for (int kt = 0; kt < nkt; kt++) {
        // load K,V tiles
        const float4* kgt = (const float4*)(kg + (size_t)kt * BKT * HD);
        const float4* vgt = (const float4*)(vg + (size_t)kt * BKT * HD);
        for (int i = tid; i < BKT * HD / 4; i += 256) {
            const int r = i >> 5, c4 = i & 31;
            float4 kv = kgt[i];
            float* d1 = &k_s[r * QSTR + c4 * 4];
            d1[0] = kv.x; d1[1] = kv.y; d1[2] = kv.z; d1[3] = kv.w;
            float4 vv = vgt[i];
            float* d2 = &v_s[r * QSTR + c4 * 4];
            d2[0] = vv.x; d2[1] = vv.y; d2[2] = vv.z; d2[3] = vv.w;
        }
        __syncthreads();

        // S = Q @ K^T   (scale folded into Q already)
        float sacc[4][4];
#pragma unroll
        for (int i = 0; i < 4; i++)
#pragma unroll
            for (int j = 0; j < 4; j++) sacc[i][j] = 0.f;

#pragma unroll 4
        for (int d4 = 0; d4 < HD / 4; d4++) {
            float4 a[4], bb[4];
#pragma unroll
            for (int i = 0; i < 4; i++)
                a[i] = *(const float4*)&q_s[(ty * 4 + i) * QSTR + d4 * 4];
#pragma unroll
            for (int j = 0; j < 4; j++)
                bb[j] = *(const float4*)&k_s[(tx * 4 + j) * QSTR + d4 * 4];
#pragma unroll
            for (int i = 0; i < 4; i++)
#pragma unroll
                for (int j = 0; j < 4; j++) {
                    sacc[i][j] = fmaf(a[i].x, bb[j].x, sacc[i][j]);
                    sacc[i][j] = fmaf(a[i].y, bb[j].y, sacc[i][j]);
                    sacc[i][j] = fmaf(a[i].z, bb[j].z, sacc[i][j]);
                    sacc[i][j] = fmaf(a[i].w, bb[j].w, sacc[i][j]);
                }
        }

        // causal mask (only the diagonal tile needs it)
        if (kt == qt) {
#pragma unroll
            for (int i = 0; i < 4; i++) {
                const int row = q0 + ty * 4 + i;
#pragma unroll
                for (int j = 0; j < 4; j++) {
                    const int col = kt * BKT + tx * 4 + j;
                    if (col > row) sacc[i][j] = -1e30f;
                }
            }
        }

        // online softmax
#pragma unroll
        for (int i = 0; i < 4; i++) {
            float mx = fmaxf(fmaxf(sacc[i][0], sacc[i][1]),
                             fmaxf(sacc[i][2], sacc[i][3]));
#pragma unroll
            for (int off = 1; off < 16; off <<= 1)
                mx = fmaxf(mx, __shfl_xor_sync(0xffffffffu, mx, off));
            const float mnew = fmaxf(m_r[i], mx);
            const float fac = __expf(m_r[i] - mnew);
            float rs = 0.f;
#pragma unroll
            for (int j = 0; j < 4; j++) {
                const float p = __expf(sacc[i][j] - mnew);
                sacc[i][j] = p;
                rs += p;
            }
#pragma unroll
            for (int off = 1; off < 16; off <<= 1)
                rs += __shfl_xor_sync(0xffffffffu, rs, off);
            l_r[i] = l_r[i] * fac + rs;
            m_r[i] = mnew;
#pragma unroll
            for (int c = 0; c < 8; c++) o[i][c] *= fac;
#pragma unroll
            for (int j = 0; j < 4; j++)
                p_s[(ty * 4 + i) * PSTR + tx * 4 + j] = sacc[i][j];
        }
        __syncthreads();

        // O += P @ V
#pragma unroll 4
        for (int j = 0; j < BKT; j++) {
            float pv[4];
#pragma unroll
            for (int i = 0; i < 4; i++) pv[i] = p_s[(ty * 4 + i) * PSTR + j];
            float4 v0 = *(const float4*)&v_s[j * QSTR + tx * 8];
            float4 v1 = *(const float4*)&v_s[j * QSTR + tx * 8 + 4];
#pragma unroll
            for (int i = 0; i < 4; i++) {
                o[i][0] = fmaf(pv[i], v0.x, o[i][0]);
                o[i][1] = fmaf(pv[i], v0.y, o[i][1]);
                o[i][2] = fmaf(pv[i], v0.z, o[i][2]);
                o[i][3] = fmaf(pv[i], v0.w, o[i][3]);
                o[i][4] = fmaf(pv[i], v1.x, o[i][4]);
                o[i][5] = fmaf(pv[i], v1.y, o[i][5]);
                o[i][6] = fmaf(pv[i], v1.z, o[i][6]);
                o[i][7] = fmaf(pv[i], v1.w, o[i][7]);
            }
        }
        __syncthreads();
    }

    // epilogue: write [b*s, h*d]
#pragma unroll
    for (int i = 0; i < 4; i++) {
        const float inv = 1.f / l_r[i];
        float* orow = &out[((size_t)(b * SS + q0 + ty * 4 + i)) * HID
                           + (size_t)h * HD + tx * 8];
        *(float4*)&orow[0] = make_float4(o[i][0] * inv, o[i][1] * inv,
                                         o[i][2] * inv, o[i][3] * inv);
        *(float4*)&orow[4] = make_float4(o[i][4] * inv, o[i][5] * inv,
                                         o[i][6] * inv, o[i][7] * inv);
    }
}

// ---------------- launch --------------------------------------------------------
extern "C" void kernel_launch(void* const* d_in, const int* in_sizes, int n_in,
                              void* d_out, int out_size)
{
    const float* hs   = (const float*)d_in[0];
    // d_in[1] = attention_mask (pure causal; applied analytically)
    const float* cosp = (const float*)d_in[2];
    const float* sinp = (const float*)d_in[3];
    const float* Wq   = (const float*)d_in[4];
    const float* Wk   = (const float*)d_in[5];
    const float* Wv   = (const float*)d_in[6];
    const float* Wo   = (const float*)d_in[7];
    float* out = (float*)d_out;

    float *lin, *qp, *kp, *vp, *ap;
    cudaGetSymbolAddress((void**)&lin, g_lin);
    cudaGetSymbolAddress((void**)&qp,  g_q);
    cudaGetSymbolAddress((void**)&kp,  g_k);
    cudaGetSymbolAddress((void**)&vp,  g_v);
    cudaGetSymbolAddress((void**)&ap,  g_attn);

    cudaFuncSetAttribute(attn_kernel,
                         cudaFuncAttributeMaxDynamicSharedMemorySize,
                         ATTN_SMEM_BYTES);

    const float qscale = 1.0f / sqrtf((float)HD);

    // Q projection + RoPE
    sgemm_nt<<<dim3(HID / 128, BSR / 128), 256>>>(hs, Wq, lin, BSR, NH * HD, HID);
    rope_kernel<<<BB * NH * SS, HD>>>(lin, cosp, sinp, qp, NH, qscale);

    // K projection + RoPE
    sgemm_nt<<<dim3(NKV * HD / 128, BSR / 128), 256>>>(hs, Wk, lin, BSR, NKV * HD, HID);
    rope_kernel<<<BB * NKV * SS, HD>>>(lin, cosp, sinp, kp, NKV, 1.0f);

    // V projection + transpose
    sgemm_nt<<<dim3(NKV * HD / 128, BSR / 128), 256>>>(hs, Wv, lin, BSR, NKV * HD, HID);
    vtrans_kernel<<<BB * NKV * SS, HD>>>(lin, vp);

    // causal attention
    attn_kernel<<<dim3(SS / BQ, NH, BB), 256, ATTN_SMEM_BYTES>>>(qp, kp, vp, ap);

    // output projection
    sgemm_nt<<<dim3(HID / 128, BSR / 128), 256>>>(ap, Wo, out, BSR, HID, HID);
}

// round 3
// speedup vs baseline: 1.4656x; 1.4656x over previous
#include <cuda_runtime.h>
#include <math.h>
#include <stdint.h>

#define BB 2
#define SS 2048
#define HID 4096
#define NH 32
#define NKV 8
#define HD 128
#define BSR (BB*SS)          // 4096 total rows
#define NREP (NH/NKV)        // 4

// ---------------- scratch (__device__ globals; no allocation allowed) ----------
__device__ float g_lin[(size_t)BSR * HID];            // 64MB: q/k/v linear scratch
__device__ float g_q [(size_t)BB * NH  * SS * HD];    // 64MB: [b,h,s,d]
__device__ float g_k [(size_t)BB * NKV * SS * HD];    // 16MB
__device__ float g_v [(size_t)BB * NKV * SS * HD];    // 16MB
__device__ float g_attn[(size_t)BSR * HID];           // 64MB: [b*s, h*d]

// ---------------- tf32 tensor-core NT GEMM: C[m,n] = sum_k A[m,k]*B[n,k] -------
// BM=BN=128, BK=32, 256 threads (8 warps), warp tile 64x32 via m16n8k8 mma.
// Shared tiles are k-major [BK][BM+4]; pad 132 makes fragment reads
// (addr = 132*k + m, k in 0..3 quad, m in 8-run) conflict-free: (4k+m)%32 distinct.
__device__ __forceinline__ uint32_t f2tf32(float x) {
    uint32_t o;
    asm("cvt.rna.tf32.f32 %0, %1;" : "=r"(o) : "f"(x));
    return o;
}

__global__ __launch_bounds__(256) void tf32gemm_nt(
    const float* __restrict__ A, const float* __restrict__ Bm,
    float* __restrict__ C, int M, int N, int K)
{
    __shared__ uint32_t As[32][132];   // [k][m]
    __shared__ uint32_t Bs[32][132];   // [k][n]

    const int tid  = threadIdx.x;
    const int warp = tid >> 5;
    const int lane = tid & 31;
    const int qr = lane >> 2;          // 0..7
    const int qc = lane & 3;           // 0..3
    const int m0 = blockIdx.y * 128;
    const int n0 = blockIdx.x * 128;
    const int warp_m = (warp >> 2) * 64;   // 0 or 64
    const int warp_n = (warp & 3) * 32;    // 0,32,64,96

    const int ldrow = tid >> 3;        // 0..31
    const int ldc4  = (tid & 7) * 4;   // 0,4,...,28

    float acc[4][4][4];
#pragma unroll
    for (int mt = 0; mt < 4; mt++)
#pragma unroll
        for (int nt = 0; nt < 4; nt++)
#pragma unroll
            for (int r = 0; r < 4; r++) acc[mt][nt][r] = 0.f;

    for (int k0 = 0; k0 < K; k0 += 32) {
        // global -> shared with transpose + tf32 rounding
#pragma unroll
        for (int it = 0; it < 4; it++) {
            const int row = ldrow + it * 32;
            float4 av = *(const float4*)&A[(size_t)(m0 + row) * K + k0 + ldc4];
            As[ldc4 + 0][row] = f2tf32(av.x);
            As[ldc4 + 1][row] = f2tf32(av.y);
            As[ldc4 + 2][row] = f2tf32(av.z);
            As[ldc4 + 3][row] = f2tf32(av.w);
            float4 bv = *(const float4*)&Bm[(size_t)(n0 + row) * K + k0 + ldc4];
            Bs[ldc4 + 0][row] = f2tf32(bv.x);
            Bs[ldc4 + 1][row] = f2tf32(bv.y);
            Bs[ldc4 + 2][row] = f2tf32(bv.z);
            Bs[ldc4 + 3][row] = f2tf32(bv.w);
        }
        __syncthreads();

#pragma unroll
        for (int kk = 0; kk < 32; kk += 8) {
            uint32_t af[4][4];
            uint32_t bf[4][2];
#pragma unroll
            for (int mt = 0; mt < 4; mt++) {
                const int r = warp_m + mt * 16 + qr;
                af[mt][0] = As[kk + qc][r];
                af[mt][1] = As[kk + qc][r + 8];
                af[mt][2] = As[kk + qc + 4][r];
                af[mt][3] = As[kk + qc + 4][r + 8];
            }
#pragma unroll
            for (int nt = 0; nt < 4; nt++) {
                const int cn = warp_n + nt * 8 + qr;
                bf[nt][0] = Bs[kk + qc][cn];
                bf[nt][1] = Bs[kk + qc + 4][cn];
            }
#pragma unroll
            for (int mt = 0; mt < 4; mt++)
#pragma unroll
                for (int nt = 0; nt < 4; nt++) {
                    asm volatile(
                        "mma.sync.aligned.m16n8k8.row.col.f32.tf32.tf32.f32 "
                        "{%0,%1,%2,%3}, {%4,%5,%6,%7}, {%8,%9}, {%0,%1,%2,%3};"
                        : "+f"(acc[mt][nt][0]), "+f"(acc[mt][nt][1]),
                          "+f"(acc[mt][nt][2]), "+f"(acc[mt][nt][3])
                        : "r"(af[mt][0]), "r"(af[mt][1]),
                          "r"(af[mt][2]), "r"(af[mt][3]),
                          "r"(bf[nt][0]), "r"(bf[nt][1]));
                }
        }
        __syncthreads();
    }

    // epilogue: c0,c1 -> (row, 2*qc), (row, 2*qc+1); c2,c3 -> row+8
#pragma unroll
    for (int mt = 0; mt < 4; mt++) {
        const int row = m0 + warp_m + mt * 16 + qr;
#pragma unroll
        for (int nt = 0; nt < 4; nt++) {
            const int col = n0 + warp_n + nt * 8 + 2 * qc;
            *(float2*)&C[(size_t)row * N + col] =
                make_float2(acc[mt][nt][0], acc[mt][nt][1]);
            *(float2*)&C[(size_t)(row + 8) * N + col] =
                make_float2(acc[mt][nt][2], acc[mt][nt][3]);
        }
    }
}

// ---------------- RoPE + [b,s,h,d] -> [b,h,s,d] transpose ----------------------
__global__ __launch_bounds__(HD) void rope_kernel(
    const float* __restrict__ lin, const float* __restrict__ cp,
    const float* __restrict__ sp, float* __restrict__ out,
    int nh, float scale)
{
    const int idx = blockIdx.x;
    const int s  = idx % SS;
    const int bh = idx / SS;
    const int h  = bh % nh;
    const int b  = bh / nh;
    const int d  = threadIdx.x;

    const size_t in_row = ((size_t)(b * SS + s)) * (size_t)(nh * HD) + (size_t)h * HD;
    const float x  = lin[in_row + d];
    const float xr = (d < HD / 2) ? -lin[in_row + d + HD / 2] : lin[in_row + d - HD / 2];
    const size_t cs = ((size_t)b * SS + s) * HD + d;
    out[(size_t)idx * HD + d] = (x * cp[cs] + xr * sp[cs]) * scale;
}

// ---------------- V transpose [b,s,kv,d] -> [b,kv,s,d] -------------------------
__global__ __launch_bounds__(HD) void vtrans_kernel(
    const float* __restrict__ lin, float* __restrict__ out)
{
    const int idx = blockIdx.x;
    const int s  = idx % SS;
    const int bh = idx / SS;
    const int h  = bh % NKV;
    const int b  = bh / NKV;
    const int d  = threadIdx.x;
    out[(size_t)idx * HD + d] =
        lin[((size_t)(b * SS + s)) * (size_t)(NKV * HD) + (size_t)h * HD + d];
}

// ---------------- causal flash attention (fp32, online softmax) ----------------
#define BQ 64
#define BKT 64
#define QSTR 132
#define PSTR 65
#define ATTN_SMEM_FLOATS (BQ*QSTR + BKT*QSTR + BKT*QSTR + BQ*PSTR)
#define ATTN_SMEM_BYTES  (ATTN_SMEM_FLOATS * 4)

__global__ __launch_bounds__(256) void attn_kernel(
    const float* __restrict__ q, const float* __restrict__ k,
    const float* __restrict__ v, float* __restrict__ out)
{
    extern __shared__ float smem[];
    float* q_s = smem;
    float* k_s = q_s + BQ * QSTR;
    float* v_s = k_s + BKT * QSTR;
    float* p_s = v_s + BKT * QSTR;

    const int tid = threadIdx.x;
    const int ty = tid >> 4;
    const int tx = tid & 15;
    const int qt = blockIdx.x;
    const int h  = blockIdx.y;
    const int b  = blockIdx.z;
    const int q0 = qt * BQ;
    const int hk = h / NREP;

    const float* qg = q + ((size_t)((b * NH + h) * SS) + q0) * HD;
    const float* kg = k + ((size_t)(b * NKV + hk) * SS) * HD;
    const float* vg = v + ((size_t)(b * NKV + hk) * SS) * HD;

    for (int i = tid; i < BQ * HD / 4; i += 256) {
        const int r = i >> 5, c4 = i & 31;
        float4 val = ((const float4*)qg)[i];
        float* dst = &q_s[r * QSTR + c4 * 4];
        dst[0] = val.x; dst[1] = val.y; dst[2] = val.z; dst[3] = val.w;
    }
    __syncthreads();

    float m_r[4], l_r[4], o[4][8];
#pragma unroll
    for (int i = 0; i < 4; i++) {
        m_r[i] = -1e30f; l_r[i] = 0.f;
#pragma unroll
        for (int c = 0; c < 8; c++) o[i][c] = 0.f;
    }

    const int nkt = qt + 1;
    for (int kt = 0; kt < nkt; kt++) {
        const float4* kgt = (const float4*)(kg + (size_t)kt * BKT * HD);
        const float4* vgt = (const float4*)(vg + (size_t)kt * BKT * HD);
        for (int i = tid; i < BKT * HD / 4; i += 256) {
            const int r = i >> 5, c4 = i & 31;
            float4 kv = kgt[i];
            float* d1 = &k_s[r * QSTR + c4 * 4];
            d1[0] = kv.x; d1[1] = kv.y; d1[2] = kv.z; d1[3] = kv.w;
            float4 vv = vgt[i];
            float* d2 = &v_s[r * QSTR + c4 * 4];
            d2[0] = vv.x; d2[1] = vv.y; d2[2] = vv.z; d2[3] = vv.w;
        }
        __syncthreads();

        float sacc[4][4];
#pragma unroll
        for (int i = 0; i < 4; i++)
#pragma unroll
            for (int j = 0; j < 4; j++) sacc[i][j] = 0.f;

#pragma unroll 4
        for (int d4 = 0; d4 < HD / 4; d4++) {
            float4 a[4], bb[4];
#pragma unroll
            for (int i = 0; i < 4; i++)
                a[i] = *(const float4*)&q_s[(ty * 4 + i) * QSTR + d4 * 4];
#pragma unroll
            for (int j = 0; j < 4; j++)
                bb[j] = *(const float4*)&k_s[(tx * 4 + j) * QSTR + d4 * 4];
#pragma unroll
            for (int i = 0; i < 4; i++)
#pragma unroll
                for (int j = 0; j < 4; j++) {
                    sacc[i][j] = fmaf(a[i].x, bb[j].x, sacc[i][j]);
                    sacc[i][j] = fmaf(a[i].y, bb[j].y, sacc[i][j]);
                    sacc[i][j] = fmaf(a[i].z, bb[j].z, sacc[i][j]);
                    sacc[i][j] = fmaf(a[i].w, bb[j].w, sacc[i][j]);
                }
        }

        if (kt == qt) {
#pragma unroll
            for (int i = 0; i < 4; i++) {
                const int row = q0 + ty * 4 + i;
#pragma unroll
                for (int j = 0; j < 4; j++) {
                    const int col = kt * BKT + tx * 4 + j;
                    if (col > row) sacc[i][j] = -1e30f;
                }
            }
        }

#pragma unroll
        for (int i = 0; i < 4; i++) {
            float mx = fmaxf(fmaxf(sacc[i][0], sacc[i][1]),
                             fmaxf(sacc[i][2], sacc[i][3]));
#pragma unroll
            for (int off = 1; off < 16; off <<= 1)
                mx = fmaxf(mx, __shfl_xor_sync(0xffffffffu, mx, off));
            const float mnew = fmaxf(m_r[i], mx);
            const float fac = __expf(m_r[i] - mnew);
            float rs = 0.f;
#pragma unroll
            for (int j = 0; j < 4; j++) {
                const float p = __expf(sacc[i][j] - mnew);
                sacc[i][j] = p;
                rs += p;
            }
#pragma unroll
            for (int off = 1; off < 16; off <<= 1)
                rs += __shfl_xor_sync(0xffffffffu, rs, off);
            l_r[i] = l_r[i] * fac + rs;
            m_r[i] = mnew;
#pragma unroll
            for (int c = 0; c < 8; c++) o[i][c] *= fac;
#pragma unroll
            for (int j = 0; j < 4; j++)
                p_s[(ty * 4 + i) * PSTR + tx * 4 + j] = sacc[i][j];
        }
        __syncthreads();

#pragma unroll 4
        for (int j = 0; j < BKT; j++) {
            float pv[4];
#pragma unroll
            for (int i = 0; i < 4; i++) pv[i] = p_s[(ty * 4 + i) * PSTR + j];
            float4 v0 = *(const float4*)&v_s[j * QSTR + tx * 8];
            float4 v1 = *(const float4*)&v_s[j * QSTR + tx * 8 + 4];
#pragma unroll
            for (int i = 0; i < 4; i++) {
                o[i][0] = fmaf(pv[i], v0.x, o[i][0]);
                o[i][1] = fmaf(pv[i], v0.y, o[i][1]);
                o[i][2] = fmaf(pv[i], v0.z, o[i][2]);
                o[i][3] = fmaf(pv[i], v0.w, o[i][3]);
                o[i][4] = fmaf(pv[i], v1.x, o[i][4]);
                o[i][5] = fmaf(pv[i], v1.y, o[i][5]);
                o[i][6] = fmaf(pv[i], v1.z, o[i][6]);
                o[i][7] = fmaf(pv[i], v1.w, o[i][7]);
            }
        }
        __syncthreads();
    }

#pragma unroll
    for (int i = 0; i < 4; i++) {
        const float inv = 1.f / l_r[i];
        float* orow = &out[((size_t)(b * SS + q0 + ty * 4 + i)) * HID
                           + (size_t)h * HD + tx * 8];
        *(float4*)&orow[0] = make_float4(o[i][0] * inv, o[i][1] * inv,
                                         o[i][2] * inv, o[i][3] * inv);
        *(float4*)&orow[4] = make_float4(o[i][4] * inv, o[i][5] * inv,
                                         o[i][6] * inv, o[i][7] * inv);
    }
}

// ---------------- launch --------------------------------------------------------
extern "C" void kernel_launch(void* const* d_in, const int* in_sizes, int n_in,
                              void* d_out, int out_size)
{
    const float* hs   = (const float*)d_in[0];
    const float* cosp = (const float*)d_in[2];
    const float* sinp = (const float*)d_in[3];
    const float* Wq   = (const float*)d_in[4];
    const float* Wk   = (const float*)d_in[5];
    const float* Wv   = (const float*)d_in[6];
    const float* Wo   = (const float*)d_in[7];
    float* out = (float*)d_out;

    float *lin, *qp, *kp, *vp, *ap;
    cudaGetSymbolAddress((void**)&lin, g_lin);
    cudaGetSymbolAddress((void**)&qp,  g_q);
    cudaGetSymbolAddress((void**)&kp,  g_k);
    cudaGetSymbolAddress((void**)&vp,  g_v);
    cudaGetSymbolAddress((void**)&ap,  g_attn);

    cudaFuncSetAttribute(attn_kernel,
                         cudaFuncAttributeMaxDynamicSharedMemorySize,
                         ATTN_SMEM_BYTES);

    const float qscale = 1.0f / sqrtf((float)HD);

    // Q projection + RoPE
    tf32gemm_nt<<<dim3(HID / 128, BSR / 128), 256>>>(hs, Wq, lin, BSR, NH * HD, HID);
    rope_kernel<<<BB * NH * SS, HD>>>(lin, cosp, sinp, qp, NH, qscale);

    // K projection + RoPE
    tf32gemm_nt<<<dim3(NKV * HD / 128, BSR / 128), 256>>>(hs, Wk, lin, BSR, NKV * HD, HID);
    rope_kernel<<<BB * NKV * SS, HD>>>(lin, cosp, sinp, kp, NKV, 1.0f);

    // V projection + transpose
    tf32gemm_nt<<<dim3(NKV * HD / 128, BSR / 128), 256>>>(hs, Wv, lin, BSR, NKV * HD, HID);
    vtrans_kernel<<<BB * NKV * SS, HD>>>(lin, vp);

    // causal attention
    attn_kernel<<<dim3(SS / BQ, NH, BB), 256, ATTN_SMEM_BYTES>>>(qp, kp, vp, ap);

    // output projection
    tf32gemm_nt<<<dim3(HID / 128, BSR / 128), 256>>>(ap, Wo, out, BSR, HID, HID);
}